// round 10
// baseline (speedup 1.0000x reference)
#include <cuda_runtime.h>
#include <math.h>
#include <stdint.h>

#define NN 100000
#define EE 1600000
#define FF 64
#define HH 128
#define GG 256
#define EPB 256
#define ETHREADS 512

// smem float offsets
#define SMF_W 0          // weights image [192][128] swizzled = 24576 floats
#define SMF_H 24576      // h [256][128] swizzled = 32768 floats
#define SMF_B2 57344     // 128
#define SMF_B3 57472     // 64
#define EDGE_SMEM (57536 * 4)   // 230144 B <= 232448

// scratch (static __device__ arrays: the sanctioned no-alloc workaround)
__device__ float g_Apre[(size_t)NN*HH];
__device__ float g_Bpre[(size_t)NN*HH];
__device__ float g_x1[(size_t)NN*FF];
__device__ float g_x2[(size_t)NN*FF];
__device__ float g_wimg[24576];   // rows 0-127: W2^T; rows 128-191: W3^T (swizzled, tf32)

__device__ __forceinline__ float silu_f(float v) {
    return __fdividef(v, 1.0f + __expf(-v));
}
__device__ __forceinline__ float to_tf32(float x) {
    float r; asm("cvt.rna.tf32.f32 %0, %1;" : "=f"(r) : "f"(x)); return r;
}
__device__ __forceinline__ void mma8(float* d, const unsigned* a, unsigned b0, unsigned b1) {
    asm volatile("mma.sync.aligned.m16n8k8.row.col.f32.tf32.tf32.f32 "
        "{%0,%1,%2,%3}, {%4,%5,%6,%7}, {%8,%9}, {%0,%1,%2,%3};"
        : "+f"(d[0]), "+f"(d[1]), "+f"(d[2]), "+f"(d[3])
        : "r"(a[0]), "r"(a[1]), "r"(a[2]), "r"(a[3]), "r"(b0), "r"(b1));
}
__device__ __forceinline__ void red_v4(float* p, float a, float b, float c, float d) {
    asm volatile("red.global.add.v4.f32 [%0], {%1,%2,%3,%4};"
                 :: "l"(p), "f"(a), "f"(b), "f"(c), "f"(d) : "memory");
}

// ---------------------------------------------------------------------------
// Weight image: combined [192 rows][128 k] XOR-swizzled, transposed, tf32.
//   rows 0..127  : W2^T  (row n holds W2[k][n] over k)
//   rows 128..191: W3^T
// word(row, k) = row*128 + (k ^ ((row & 7) << 2))
// ---------------------------------------------------------------------------
__global__ void __launch_bounds__(256) make_wimg_kernel(
    const float* __restrict__ W2l, const float* __restrict__ W3l, float* __restrict__ img)
{
    int tid = threadIdx.x + blockIdx.x * 256;
    int stride = gridDim.x * 256;
    for (int idx = tid; idx < 16384; idx += stride) {
        int n = idx >> 7, k = idx & 127;
        img[n*128 + (k ^ ((n & 7) << 2))] = to_tf32(W2l[k*128 + n]);
    }
    for (int idx = tid; idx < 8192; idx += stride) {
        int n = idx >> 7, k = idx & 127;
        img[(128 + n)*128 + (k ^ ((n & 7) << 2))] = to_tf32(W3l[k*64 + n]);
    }
}

// ---------------------------------------------------------------------------
// Precompute Apre = x @ W1[0:64] + b1, Bpre = x[:,3:] @ W1[64:125]
// ---------------------------------------------------------------------------
__global__ void __launch_bounds__(256) precomp_kernel(
    const float* __restrict__ xin, const float* __restrict__ W1l, const float* __restrict__ b1l,
    float* __restrict__ Apre, float* __restrict__ Bpre)
{
    __shared__ float xs[32*64];
    int tid = threadIdx.x;
    size_t nb = (size_t)blockIdx.x * 32;

    const float4* xg = (const float4*)(xin + nb*64);
    float4* xs4 = (float4*)xs;
#pragma unroll
    for (int i = 0; i < 2; ++i) xs4[tid + i*256] = xg[tid + i*256];
    __syncthreads();

    int part = blockIdx.y;
    int tx = tid & 31, ty = tid >> 5;
    float acc[4][4];
#pragma unroll
    for (int a = 0; a < 4; ++a)
#pragma unroll
        for (int b = 0; b < 4; ++b) acc[a][b] = 0.f;

    int cbeg = part ? 3 : 0;
    const float* Wb = part ? (W1l + 61*128) : W1l;
    for (int c = cbeg; c < 64; ++c) {
        float4 w = *(const float4*)(Wb + c*128 + tx*4);
#pragma unroll
        for (int ni = 0; ni < 4; ++ni) {
            float a = xs[(ty*4+ni)*64 + c];
            acc[ni][0] += a*w.x; acc[ni][1] += a*w.y;
            acc[ni][2] += a*w.z; acc[ni][3] += a*w.w;
        }
    }

    float4 bv = make_float4(0.f,0.f,0.f,0.f);
    float* outp;
    if (part) outp = Bpre;
    else { outp = Apre; bv = *(const float4*)(b1l + tx*4); }
#pragma unroll
    for (int ni = 0; ni < 4; ++ni) {
        float4 r = make_float4(acc[ni][0]+bv.x, acc[ni][1]+bv.y, acc[ni][2]+bv.z, acc[ni][3]+bv.w);
        *(float4*)(outp + (nb + ty*4 + ni)*128 + tx*4) = r;
    }
}

// ---------------------------------------------------------------------------
// Fused edge kernel: gather h1 (tf32) -> tf32 MMA (h1@W2) -> silu -> tf32 MMA
// (h2@W3) -> silu -> vectorized red.v4 scatter. 256 edges/block, 16 warps.
// ---------------------------------------------------------------------------
__global__ void __launch_bounds__(ETHREADS, 1) edge_kernel(
    const float* __restrict__ Apre, const float* __restrict__ Bpre, const float* __restrict__ xin,
    const int* __restrict__ srcp, const int* __restrict__ dstp,
    const float* __restrict__ wdrow, const float* __restrict__ wimg, const float* __restrict__ b2l,
    const float* __restrict__ b3l, float* __restrict__ xout)
{
    extern __shared__ float sm[];
    float* Ws  = sm + SMF_W;
    float* hs  = sm + SMF_H;
    float* b2s = sm + SMF_B2;
    float* b3s = sm + SMF_B3;

    const int tid = threadIdx.x;
    const int w = tid >> 5, lane = tid & 31;
    const int g = lane >> 2, tig = lane & 3;
    const int eb = blockIdx.x * EPB;

    // stage weight image + biases
    {
        const float4* gw = (const float4*)wimg;
        float4* sw = (float4*)Ws;
#pragma unroll
        for (int i = 0; i < 12; ++i) sw[tid + i*512] = gw[tid + i*512];
        if (tid < 128) b2s[tid] = b2l[tid];
        else if (tid < 192) b3s[tid-128] = b3l[tid-128];
    }

    // gather h1: warp covers 16 edges, lane covers k-chunk lane*4..lane*4+3
    {
        float4 wd4 = __ldg((const float4*)(wdrow + lane*4));
        int ids = (lane < 16) ? __ldg(srcp + eb + w*16 + lane)
                              : __ldg(dstp + eb + w*16 + (lane - 16));
#pragma unroll 4
        for (int it = 0; it < 16; ++it) {
            int s = __shfl_sync(0xffffffffu, ids, it);
            int d = __shfl_sync(0xffffffffu, ids, 16 + it);
            float4 xs4 = __ldg((const float4*)(xin + (size_t)s*64));
            float4 xd4 = __ldg((const float4*)(xin + (size_t)d*64));
            float dx = xs4.x - xd4.x, dy = xs4.y - xd4.y, dz = xs4.z - xd4.z;
            float dist2 = dx*dx + dy*dy + dz*dz;
            float4 a = __ldg((const float4*)(Apre + (size_t)d*128 + lane*4));
            float4 b = __ldg((const float4*)(Bpre + (size_t)s*128 + lane*4));
            float4 v;
            v.x = to_tf32(silu_f(a.x + b.x + dist2*wd4.x));
            v.y = to_tf32(silu_f(a.y + b.y + dist2*wd4.y));
            v.z = to_tf32(silu_f(a.z + b.z + dist2*wd4.z));
            v.w = to_tf32(silu_f(a.w + b.w + dist2*wd4.w));
            int e = w*16 + it;
            int word = e*128 + ((lane*4) ^ ((e & 7) << 2));
            *(float4*)(hs + word) = v;
        }
    }
    __syncthreads();

    const int e0 = (w & 7) * 32;
    const int n0 = (w >> 3) * 64;
    const int xm = g << 2;
    const float* hA0 = hs + (e0 + g) * 128;
    const float* hA1 = hs + (e0 + g + 8) * 128;
    const float* hA2 = hs + (e0 + g + 16) * 128;
    const float* hA3 = hs + (e0 + g + 24) * 128;

    // ---- GEMM2: [256e x 128] = h1 @ W2 ----
    float acc[2][8][4];
#pragma unroll
    for (int mf = 0; mf < 2; ++mf)
#pragma unroll
        for (int nf = 0; nf < 8; ++nf)
#pragma unroll
            for (int q = 0; q < 4; ++q) acc[mf][nf][q] = 0.f;

#pragma unroll
    for (int ks = 0; ks < 16; ++ks) {
        int off1 = (ks*8 + tig) ^ xm;
        int off2 = (ks*8 + tig + 4) ^ xm;
        unsigned a[2][4];
        a[0][0] = __float_as_uint(hA0[off1]);
        a[0][1] = __float_as_uint(hA1[off1]);
        a[0][2] = __float_as_uint(hA0[off2]);
        a[0][3] = __float_as_uint(hA1[off2]);
        a[1][0] = __float_as_uint(hA2[off1]);
        a[1][1] = __float_as_uint(hA3[off1]);
        a[1][2] = __float_as_uint(hA2[off2]);
        a[1][3] = __float_as_uint(hA3[off2]);
#pragma unroll
        for (int nf = 0; nf < 8; ++nf) {
            const float* Wn = Ws + (n0 + nf*8 + g) * 128;
            unsigned b0 = __float_as_uint(Wn[off1]);
            unsigned b1 = __float_as_uint(Wn[off2]);
            mma8(acc[0][nf], a[0], b0, b1);
            mma8(acc[1][nf], a[1], b0, b1);
        }
    }
    __syncthreads();   // all h1 reads complete before h2 overwrites

    // ---- epilogue1: h2 = tf32(silu(D2 + b2)) back into hs ----
#pragma unroll
    for (int mf = 0; mf < 2; ++mf) {
        int elo = e0 + mf*16 + g;
        float* hlo = hs + elo*128;
        float* hhi = hs + (elo + 8)*128;
#pragma unroll
        for (int nf = 0; nf < 8; ++nf) {
            int n = n0 + nf*8 + 2*tig;
            float bb0 = b2s[n], bb1 = b2s[n+1];
            float2 vlo, vhi;
            vlo.x = to_tf32(silu_f(acc[mf][nf][0] + bb0));
            vlo.y = to_tf32(silu_f(acc[mf][nf][1] + bb1));
            vhi.x = to_tf32(silu_f(acc[mf][nf][2] + bb0));
            vhi.y = to_tf32(silu_f(acc[mf][nf][3] + bb1));
            int woff = n ^ xm;
            *(float2*)(hlo + woff) = vlo;
            *(float2*)(hhi + woff) = vhi;
        }
    }
    __syncthreads();

    // ---- GEMM3: [256e x 64] = h2 @ W3 ----
    const int n03 = (w >> 3) * 32;
    float acc3[2][4][4];
#pragma unroll
    for (int mf = 0; mf < 2; ++mf)
#pragma unroll
        for (int nf = 0; nf < 4; ++nf)
#pragma unroll
            for (int q = 0; q < 4; ++q) acc3[mf][nf][q] = 0.f;

#pragma unroll
    for (int ks = 0; ks < 16; ++ks) {
        int off1 = (ks*8 + tig) ^ xm;
        int off2 = (ks*8 + tig + 4) ^ xm;
        unsigned a[2][4];
        a[0][0] = __float_as_uint(hA0[off1]);
        a[0][1] = __float_as_uint(hA1[off1]);
        a[0][2] = __float_as_uint(hA0[off2]);
        a[0][3] = __float_as_uint(hA1[off2]);
        a[1][0] = __float_as_uint(hA2[off1]);
        a[1][1] = __float_as_uint(hA3[off1]);
        a[1][2] = __float_as_uint(hA2[off2]);
        a[1][3] = __float_as_uint(hA3[off2]);
#pragma unroll
        for (int nf = 0; nf < 4; ++nf) {
            const float* Wn = Ws + (128 + n03 + nf*8 + g) * 128;
            unsigned b0 = __float_as_uint(Wn[off1]);
            unsigned b1 = __float_as_uint(Wn[off2]);
            mma8(acc3[0][nf], a[0], b0, b1);
            mma8(acc3[1][nf], a[1], b0, b1);
        }
    }

    // ---- epilogue2: silu(D3 + b3); pair-shuffle to 4-contiguous cols; red.v4 ----
    // Fragment: thread holds cols (2*tig, 2*tig+1) of rows elo (c0,c1) and elo+8 (c2,c3).
    // Exchange within tig-pair (lane^1): even lane assembles cols 4q..4q+3 of row elo,
    // odd lane assembles same cols of row elo+8. One red.global.add.v4.f32 each.
#pragma unroll
    for (int mf = 0; mf < 2; ++mf) {
        int elo = e0 + mf*16 + g;
        int dlo = __ldg(dstp + eb + elo);
        int dhi = __ldg(dstp + eb + elo + 8);
        float* plo = xout + (size_t)dlo*64;
        float* phi = xout + (size_t)dhi*64;
        bool odd = (tig & 1);
        int cbase = n03 + (tig >> 1) * 4;
#pragma unroll
        for (int nf = 0; nf < 4; ++nf) {
            int n = n03 + nf*8 + 2*tig;
            float bb0 = b3s[n], bb1 = b3s[n+1];
            float v0 = silu_f(acc3[mf][nf][0] + bb0);
            float v1 = silu_f(acc3[mf][nf][1] + bb1);
            float v2 = silu_f(acc3[mf][nf][2] + bb0);
            float v3 = silu_f(acc3[mf][nf][3] + bb1);
            // even lane sends its row-hi pair, odd lane sends its row-lo pair
            unsigned long long sendv = odd ? (((unsigned long long)__float_as_uint(v1) << 32) | __float_as_uint(v0))
                                           : (((unsigned long long)__float_as_uint(v3) << 32) | __float_as_uint(v2));
            unsigned long long recv = __shfl_xor_sync(0xffffffffu, sendv, 1);
            float r0 = __uint_as_float((unsigned)recv);
            float r1 = __uint_as_float((unsigned)(recv >> 32));
            float* p = odd ? phi : plo;
            float a0 = odd ? r0 : v0;
            float a1 = odd ? r1 : v1;
            float a2 = odd ? v2 : r0;
            float a3 = odd ? v3 : r1;
            red_v4(p + cbase + nf*8, a0, a1, a2, a3);
        }
    }
}

// ---------------------------------------------------------------------------
// Pooling + readout MLP (unchanged)
// ---------------------------------------------------------------------------
__global__ void __launch_bounds__(64) pool_head_kernel(
    const float* __restrict__ xf, const int* __restrict__ batch, const float* __restrict__ u,
    const float* __restrict__ LW1, const float* __restrict__ Lb1,
    const float* __restrict__ LW2, const float* __restrict__ Lb2,
    const float* __restrict__ LW3, const float* __restrict__ Lb3,
    float* __restrict__ out)
{
    __shared__ float pooled[194];
    __shared__ float hbuf[64];
    int g = blockIdx.x, f = threadIdx.x;

    int start, end;
    {
        int lo = 0, hi = NN;
        while (lo < hi) { int m = (lo+hi) >> 1; if (batch[m] < g) lo = m+1; else hi = m; }
        start = lo;
        hi = NN;
        while (lo < hi) { int m = (lo+hi) >> 1; if (batch[m] < g+1) lo = m+1; else hi = m; }
        end = lo;
    }

    float s = 0.f, mx = -3.402823466e38f;
    for (int n = start; n < end; ++n) {
        float v = xf[(size_t)n*64 + f];
        s += v; mx = fmaxf(mx, v);
    }
    float cnt = fmaxf((float)(end - start), 1.f);
    pooled[f]      = s;
    pooled[64+f]   = s / cnt;
    pooled[128+f]  = mx;
    if (f < 2) pooled[192+f] = u[g*2+f];
    __syncthreads();

    float a = Lb1[f];
    for (int c = 0; c < 194; ++c) a += pooled[c] * LW1[c*64+f];
    float h = silu_f(a);
    hbuf[f] = h;
    __syncthreads();

    a = Lb2[f];
    for (int c = 0; c < 64; ++c) a += hbuf[c] * LW2[c*64+f];
    h = silu_f(a);
    __syncthreads();
    hbuf[f] = h;
    __syncthreads();

    if (f < 2) {
        a = Lb3[f];
        for (int c = 0; c < 64; ++c) a += hbuf[c] * LW3[c*2+f];
        out[g*2+f] = a;
    }
}

// ---------------------------------------------------------------------------
extern "C" void kernel_launch(void* const* d_in, const int* in_sizes, int n_in,
                              void* d_out, int out_size) {
    const float* x    = (const float*)d_in[0];
    const float* u    = (const float*)d_in[1];
    const int*   ei   = (const int*)d_in[2];
    const int*   batch= (const int*)d_in[3];
    const float* W1   = (const float*)d_in[4];
    const float* b1   = (const float*)d_in[5];
    const float* W2   = (const float*)d_in[6];
    const float* b2   = (const float*)d_in[7];
    const float* W3   = (const float*)d_in[8];
    const float* b3   = (const float*)d_in[9];
    const float* LW1  = (const float*)d_in[10];
    const float* Lb1  = (const float*)d_in[11];
    const float* LW2  = (const float*)d_in[12];
    const float* Lb2  = (const float*)d_in[13];
    const float* LW3  = (const float*)d_in[14];
    const float* Lb3  = (const float*)d_in[15];
    float* out = (float*)d_out;

    float *Apre, *Bpre, *x1, *x2, *wimg;
    cudaGetSymbolAddress((void**)&Apre, g_Apre);
    cudaGetSymbolAddress((void**)&Bpre, g_Bpre);
    cudaGetSymbolAddress((void**)&x1,   g_x1);
    cudaGetSymbolAddress((void**)&x2,   g_x2);
    cudaGetSymbolAddress((void**)&wimg, g_wimg);

    cudaFuncSetAttribute(edge_kernel, cudaFuncAttributeMaxDynamicSharedMemorySize, EDGE_SMEM);

    const int* srcp = ei;
    const int* dstp = ei + EE;

    for (int l = 0; l < 2; ++l) {
        const float* xin = l ? (const float*)x1 : x;
        float* xout = l ? x2 : x1;
        precomp_kernel<<<dim3(3125, 2, 1), 256>>>(
            xin, W1 + (size_t)l*126*128, b1 + (size_t)l*128, Apre, Bpre);
        make_wimg_kernel<<<64, 256>>>(
            W2 + (size_t)l*128*128, W3 + (size_t)l*128*64, wimg);
        cudaMemsetAsync(xout, 0, (size_t)NN*FF*sizeof(float));
        edge_kernel<<<EE/EPB, ETHREADS, EDGE_SMEM>>>(
            Apre, Bpre, xin, srcp, dstp,
            W1 + (size_t)l*126*128 + 125*128,
            wimg, b2 + (size_t)l*128,
            b3 + (size_t)l*64, xout);
    }
    pool_head_kernel<<<GG, 64>>>(x2, batch, u, LW1, Lb1, LW2, Lb2, LW3, Lb3, out);
}

// round 11
// speedup vs baseline: 1.4393x; 1.4393x over previous
#include <cuda_runtime.h>
#include <math.h>
#include <stdint.h>

#define NN 100000
#define EE 1600000
#define FF 64
#define HH 128
#define GG 256
#define EPB 256
#define ETHREADS 512

// smem float offsets
#define SMF_W 0          // weights image [192][128] swizzled = 24576 floats
#define SMF_H 24576      // h [256][128] swizzled = 32768 floats
#define SMF_B2 57344     // 128
#define SMF_B3 57472     // 64
#define EDGE_SMEM (57536 * 4)   // 230144 B <= 232448

// scratch (static __device__ arrays: the sanctioned no-alloc workaround)
__device__ float g_Apre[(size_t)NN*HH];
__device__ float g_Bpre[(size_t)NN*HH];
__device__ float g_x1[(size_t)NN*FF];
__device__ float g_x2[(size_t)NN*FF];
__device__ float g_wimg[24576];   // rows 0-127: W2^T; rows 128-191: W3^T (swizzled, tf32)

__device__ __forceinline__ float silu_f(float v) {
    return __fdividef(v, 1.0f + __expf(-v));
}
// 1-MUFU silu via tanh.approx (err ~2^-10.7, below tf32 rounding of consumers)
__device__ __forceinline__ float silu_t(float v) {
    float t;
    asm("tanh.approx.f32 %0, %1;" : "=f"(t) : "f"(0.5f * v));
    return 0.5f * v * (1.0f + t);
}
__device__ __forceinline__ float to_tf32(float x) {
    float r; asm("cvt.rna.tf32.f32 %0, %1;" : "=f"(r) : "f"(x)); return r;
}
__device__ __forceinline__ void mma8(float* d, const unsigned* a, unsigned b0, unsigned b1) {
    asm volatile("mma.sync.aligned.m16n8k8.row.col.f32.tf32.tf32.f32 "
        "{%0,%1,%2,%3}, {%4,%5,%6,%7}, {%8,%9}, {%0,%1,%2,%3};"
        : "+f"(d[0]), "+f"(d[1]), "+f"(d[2]), "+f"(d[3])
        : "r"(a[0]), "r"(a[1]), "r"(a[2]), "r"(a[3]), "r"(b0), "r"(b1));
}
// packed f32x2 helpers (for precomp)
__device__ __forceinline__ void fma2(unsigned long long& d, unsigned long long a, unsigned long long b) {
    asm("fma.rn.f32x2 %0, %1, %2, %0;" : "+l"(d) : "l"(a), "l"(b));
}
__device__ __forceinline__ unsigned long long bcast2(float a) {
    unsigned long long r; asm("mov.b64 %0, {%1, %1};" : "=l"(r) : "f"(a)); return r;
}
__device__ __forceinline__ float2 unpk(unsigned long long v) {
    float2 r; asm("mov.b64 {%0, %1}, %2;" : "=f"(r.x), "=f"(r.y) : "l"(v)); return r;
}

// ---------------------------------------------------------------------------
// Weight image: combined [192 rows][128 k] XOR-swizzled, transposed, tf32.
//   rows 0..127  : W2^T  (row n holds W2[k][n] over k)
//   rows 128..191: W3^T
// word(row, k) = row*128 + (k ^ ((row & 7) << 2))
// ---------------------------------------------------------------------------
__global__ void __launch_bounds__(256) make_wimg_kernel(
    const float* __restrict__ W2l, const float* __restrict__ W3l, float* __restrict__ img)
{
    int tid = threadIdx.x + blockIdx.x * 256;
    int stride = gridDim.x * 256;
    for (int idx = tid; idx < 16384; idx += stride) {
        int n = idx >> 7, k = idx & 127;
        img[n*128 + (k ^ ((n & 7) << 2))] = to_tf32(W2l[k*128 + n]);
    }
    for (int idx = tid; idx < 8192; idx += stride) {
        int n = idx >> 7, k = idx & 127;
        img[(128 + n)*128 + (k ^ ((n & 7) << 2))] = to_tf32(W3l[k*64 + n]);
    }
}

// ---------------------------------------------------------------------------
// Precompute Apre = x @ W1[0:64] + b1, Bpre = x[:,3:] @ W1[64:125]
// packed f32x2 FMA inner loop.
// ---------------------------------------------------------------------------
__global__ void __launch_bounds__(256) precomp_kernel(
    const float* __restrict__ xin, const float* __restrict__ W1l, const float* __restrict__ b1l,
    float* __restrict__ Apre, float* __restrict__ Bpre)
{
    __shared__ float xs[32*64];
    int tid = threadIdx.x;
    size_t nb = (size_t)blockIdx.x * 32;

    const float4* xg = (const float4*)(xin + nb*64);
    float4* xs4 = (float4*)xs;
#pragma unroll
    for (int i = 0; i < 2; ++i) xs4[tid + i*256] = xg[tid + i*256];
    __syncthreads();

    int part = blockIdx.y;
    int tx = tid & 31, ty = tid >> 5;
    unsigned long long acc[4][2];
#pragma unroll
    for (int a = 0; a < 4; ++a) { acc[a][0] = 0ull; acc[a][1] = 0ull; }

    int cbeg = part ? 3 : 0;
    const float* Wb = part ? (W1l + 61*128) : W1l;
#pragma unroll 4
    for (int c = cbeg; c < 64; ++c) {
        ulonglong2 wv = *(const ulonglong2*)(Wb + c*128 + tx*4);
#pragma unroll
        for (int ni = 0; ni < 4; ++ni) {
            unsigned long long av = bcast2(xs[(ty*4+ni)*64 + c]);
            fma2(acc[ni][0], av, wv.x);
            fma2(acc[ni][1], av, wv.y);
        }
    }

    float4 bv = make_float4(0.f,0.f,0.f,0.f);
    float* outp;
    if (part) outp = Bpre;
    else { outp = Apre; bv = *(const float4*)(b1l + tx*4); }
#pragma unroll
    for (int ni = 0; ni < 4; ++ni) {
        float2 p0 = unpk(acc[ni][0]), p1 = unpk(acc[ni][1]);
        float4 r = make_float4(p0.x+bv.x, p0.y+bv.y, p1.x+bv.z, p1.y+bv.w);
        *(float4*)(outp + (nb + ty*4 + ni)*128 + tx*4) = r;
    }
}

// ---------------------------------------------------------------------------
// Fused edge kernel: gather h1 (tf32) -> tf32 MMA (h1@W2) -> silu -> tf32 MMA
// (h2@W3) -> silu -> atomic scatter. 256 edges/block, 16 warps, XOR-swizzled
// smem; warp tile 32e x 64n (GEMM2) / 32e x 32n (GEMM3).
// ---------------------------------------------------------------------------
__global__ void __launch_bounds__(ETHREADS, 1) edge_kernel(
    const float* __restrict__ Apre, const float* __restrict__ Bpre, const float* __restrict__ xin,
    const int* __restrict__ srcp, const int* __restrict__ dstp,
    const float* __restrict__ wdrow, const float* __restrict__ wimg, const float* __restrict__ b2l,
    const float* __restrict__ b3l, float* __restrict__ xout)
{
    extern __shared__ float sm[];
    float* Ws  = sm + SMF_W;
    float* hs  = sm + SMF_H;
    float* b2s = sm + SMF_B2;
    float* b3s = sm + SMF_B3;

    const int tid = threadIdx.x;
    const int w = tid >> 5, lane = tid & 31;
    const int g = lane >> 2, tig = lane & 3;
    const int eb = blockIdx.x * EPB;

    // stage weight image + biases
    {
        const float4* gw = (const float4*)wimg;
        float4* sw = (float4*)Ws;
#pragma unroll
        for (int i = 0; i < 12; ++i) sw[tid + i*512] = gw[tid + i*512];
        if (tid < 128) b2s[tid] = b2l[tid];
        else if (tid < 192) b3s[tid-128] = b3l[tid-128];
    }

    // gather h1: warp covers 16 edges, lane covers k-chunk lane*4..lane*4+3
    {
        float4 wd4 = __ldg((const float4*)(wdrow + lane*4));
        int ids = (lane < 16) ? __ldg(srcp + eb + w*16 + lane)
                              : __ldg(dstp + eb + w*16 + (lane - 16));
#pragma unroll 4
        for (int it = 0; it < 16; ++it) {
            int s = __shfl_sync(0xffffffffu, ids, it);
            int d = __shfl_sync(0xffffffffu, ids, 16 + it);
            float4 xs4 = __ldg((const float4*)(xin + (size_t)s*64));
            float4 xd4 = __ldg((const float4*)(xin + (size_t)d*64));
            float dx = xs4.x - xd4.x, dy = xs4.y - xd4.y, dz = xs4.z - xd4.z;
            float dist2 = dx*dx + dy*dy + dz*dz;
            float4 a = __ldg((const float4*)(Apre + (size_t)d*128 + lane*4));
            float4 b = __ldg((const float4*)(Bpre + (size_t)s*128 + lane*4));
            float4 v;
            v.x = to_tf32(silu_t(a.x + b.x + dist2*wd4.x));
            v.y = to_tf32(silu_t(a.y + b.y + dist2*wd4.y));
            v.z = to_tf32(silu_t(a.z + b.z + dist2*wd4.z));
            v.w = to_tf32(silu_t(a.w + b.w + dist2*wd4.w));
            int e = w*16 + it;
            int word = e*128 + ((lane*4) ^ ((e & 7) << 2));
            *(float4*)(hs + word) = v;
        }
    }
    __syncthreads();

    const int e0 = (w & 7) * 32;
    const int n0 = (w >> 3) * 64;
    const int xm = g << 2;
    const float* hA0 = hs + (e0 + g) * 128;
    const float* hA1 = hs + (e0 + g + 8) * 128;
    const float* hA2 = hs + (e0 + g + 16) * 128;
    const float* hA3 = hs + (e0 + g + 24) * 128;

    // ---- GEMM2: [256e x 128] = h1 @ W2 ----
    float acc[2][8][4];
#pragma unroll
    for (int mf = 0; mf < 2; ++mf)
#pragma unroll
        for (int nf = 0; nf < 8; ++nf)
#pragma unroll
            for (int q = 0; q < 4; ++q) acc[mf][nf][q] = 0.f;

#pragma unroll
    for (int ks = 0; ks < 16; ++ks) {
        int off1 = (ks*8 + tig) ^ xm;
        int off2 = (ks*8 + tig + 4) ^ xm;
        unsigned a[2][4];
        a[0][0] = __float_as_uint(hA0[off1]);
        a[0][1] = __float_as_uint(hA1[off1]);
        a[0][2] = __float_as_uint(hA0[off2]);
        a[0][3] = __float_as_uint(hA1[off2]);
        a[1][0] = __float_as_uint(hA2[off1]);
        a[1][1] = __float_as_uint(hA3[off1]);
        a[1][2] = __float_as_uint(hA2[off2]);
        a[1][3] = __float_as_uint(hA3[off2]);
#pragma unroll
        for (int nf = 0; nf < 8; ++nf) {
            const float* Wn = Ws + (n0 + nf*8 + g) * 128;
            unsigned b0 = __float_as_uint(Wn[off1]);
            unsigned b1 = __float_as_uint(Wn[off2]);
            mma8(acc[0][nf], a[0], b0, b1);
            mma8(acc[1][nf], a[1], b0, b1);
        }
    }
    __syncthreads();   // all h1 reads complete before h2 overwrites

    // ---- epilogue1: h2 = tf32(silu(D2 + b2)) back into hs ----
#pragma unroll
    for (int mf = 0; mf < 2; ++mf) {
        int elo = e0 + mf*16 + g;
        float* hlo = hs + elo*128;
        float* hhi = hs + (elo + 8)*128;
#pragma unroll
        for (int nf = 0; nf < 8; ++nf) {
            int n = n0 + nf*8 + 2*tig;
            float bb0 = b2s[n], bb1 = b2s[n+1];
            float2 vlo, vhi;
            vlo.x = to_tf32(silu_t(acc[mf][nf][0] + bb0));
            vlo.y = to_tf32(silu_t(acc[mf][nf][1] + bb1));
            vhi.x = to_tf32(silu_t(acc[mf][nf][2] + bb0));
            vhi.y = to_tf32(silu_t(acc[mf][nf][3] + bb1));
            int woff = n ^ xm;
            *(float2*)(hlo + woff) = vlo;
            *(float2*)(hhi + woff) = vhi;
        }
    }
    __syncthreads();

    // ---- GEMM3: [256e x 64] = h2 @ W3 ----
    const int n03 = (w >> 3) * 32;
    float acc3[2][4][4];
#pragma unroll
    for (int mf = 0; mf < 2; ++mf)
#pragma unroll
        for (int nf = 0; nf < 4; ++nf)
#pragma unroll
            for (int q = 0; q < 4; ++q) acc3[mf][nf][q] = 0.f;

#pragma unroll
    for (int ks = 0; ks < 16; ++ks) {
        int off1 = (ks*8 + tig) ^ xm;
        int off2 = (ks*8 + tig + 4) ^ xm;
        unsigned a[2][4];
        a[0][0] = __float_as_uint(hA0[off1]);
        a[0][1] = __float_as_uint(hA1[off1]);
        a[0][2] = __float_as_uint(hA0[off2]);
        a[0][3] = __float_as_uint(hA1[off2]);
        a[1][0] = __float_as_uint(hA2[off1]);
        a[1][1] = __float_as_uint(hA3[off1]);
        a[1][2] = __float_as_uint(hA2[off2]);
        a[1][3] = __float_as_uint(hA3[off2]);
#pragma unroll
        for (int nf = 0; nf < 4; ++nf) {
            const float* Wn = Ws + (128 + n03 + nf*8 + g) * 128;
            unsigned b0 = __float_as_uint(Wn[off1]);
            unsigned b1 = __float_as_uint(Wn[off2]);
            mma8(acc3[0][nf], a[0], b0, b1);
            mma8(acc3[1][nf], a[1], b0, b1);
        }
    }

    // ---- epilogue2: silu(D3 + b3), scalar atomic scatter-add (R9-proven) ----
#pragma unroll
    for (int mf = 0; mf < 2; ++mf) {
        int elo = e0 + mf*16 + g;
        int dlo = __ldg(dstp + eb + elo);
        int dhi = __ldg(dstp + eb + elo + 8);
        float* olo = xout + (size_t)dlo*64;
        float* ohi = xout + (size_t)dhi*64;
#pragma unroll
        for (int nf = 0; nf < 4; ++nf) {
            int n = n03 + nf*8 + 2*tig;
            float bb0 = b3s[n], bb1 = b3s[n+1];
            atomicAdd(olo + n,     silu_f(acc3[mf][nf][0] + bb0));
            atomicAdd(olo + n + 1, silu_f(acc3[mf][nf][1] + bb1));
            atomicAdd(ohi + n,     silu_f(acc3[mf][nf][2] + bb0));
            atomicAdd(ohi + n + 1, silu_f(acc3[mf][nf][3] + bb1));
        }
    }
}

// ---------------------------------------------------------------------------
// Pooling + readout MLP (unchanged)
// ---------------------------------------------------------------------------
__global__ void __launch_bounds__(64) pool_head_kernel(
    const float* __restrict__ xf, const int* __restrict__ batch, const float* __restrict__ u,
    const float* __restrict__ LW1, const float* __restrict__ Lb1,
    const float* __restrict__ LW2, const float* __restrict__ Lb2,
    const float* __restrict__ LW3, const float* __restrict__ Lb3,
    float* __restrict__ out)
{
    __shared__ float pooled[194];
    __shared__ float hbuf[64];
    int g = blockIdx.x, f = threadIdx.x;

    int start, end;
    {
        int lo = 0, hi = NN;
        while (lo < hi) { int m = (lo+hi) >> 1; if (batch[m] < g) lo = m+1; else hi = m; }
        start = lo;
        hi = NN;
        while (lo < hi) { int m = (lo+hi) >> 1; if (batch[m] < g+1) lo = m+1; else hi = m; }
        end = lo;
    }

    float s = 0.f, mx = -3.402823466e38f;
    for (int n = start; n < end; ++n) {
        float v = xf[(size_t)n*64 + f];
        s += v; mx = fmaxf(mx, v);
    }
    float cnt = fmaxf((float)(end - start), 1.f);
    pooled[f]      = s;
    pooled[64+f]   = s / cnt;
    pooled[128+f]  = mx;
    if (f < 2) pooled[192+f] = u[g*2+f];
    __syncthreads();

    float a = Lb1[f];
    for (int c = 0; c < 194; ++c) a += pooled[c] * LW1[c*64+f];
    float h = silu_f(a);
    hbuf[f] = h;
    __syncthreads();

    a = Lb2[f];
    for (int c = 0; c < 64; ++c) a += hbuf[c] * LW2[c*64+f];
    h = silu_f(a);
    __syncthreads();
    hbuf[f] = h;
    __syncthreads();

    if (f < 2) {
        a = Lb3[f];
        for (int c = 0; c < 64; ++c) a += hbuf[c] * LW3[c*2+f];
        out[g*2+f] = a;
    }
}

// ---------------------------------------------------------------------------
extern "C" void kernel_launch(void* const* d_in, const int* in_sizes, int n_in,
                              void* d_out, int out_size) {
    const float* x    = (const float*)d_in[0];
    const float* u    = (const float*)d_in[1];
    const int*   ei   = (const int*)d_in[2];
    const int*   batch= (const int*)d_in[3];
    const float* W1   = (const float*)d_in[4];
    const float* b1   = (const float*)d_in[5];
    const float* W2   = (const float*)d_in[6];
    const float* b2   = (const float*)d_in[7];
    const float* W3   = (const float*)d_in[8];
    const float* b3   = (const float*)d_in[9];
    const float* LW1  = (const float*)d_in[10];
    const float* Lb1  = (const float*)d_in[11];
    const float* LW2  = (const float*)d_in[12];
    const float* Lb2  = (const float*)d_in[13];
    const float* LW3  = (const float*)d_in[14];
    const float* Lb3  = (const float*)d_in[15];
    float* out = (float*)d_out;

    float *Apre, *Bpre, *x1, *x2, *wimg;
    cudaGetSymbolAddress((void**)&Apre, g_Apre);
    cudaGetSymbolAddress((void**)&Bpre, g_Bpre);
    cudaGetSymbolAddress((void**)&x1,   g_x1);
    cudaGetSymbolAddress((void**)&x2,   g_x2);
    cudaGetSymbolAddress((void**)&wimg, g_wimg);

    cudaFuncSetAttribute(edge_kernel, cudaFuncAttributeMaxDynamicSharedMemorySize, EDGE_SMEM);

    const int* srcp = ei;
    const int* dstp = ei + EE;

    for (int l = 0; l < 2; ++l) {
        const float* xin = l ? (const float*)x1 : x;
        float* xout = l ? x2 : x1;
        precomp_kernel<<<dim3(3125, 2, 1), 256>>>(
            xin, W1 + (size_t)l*126*128, b1 + (size_t)l*128, Apre, Bpre);
        make_wimg_kernel<<<64, 256>>>(
            W2 + (size_t)l*128*128, W3 + (size_t)l*128*64, wimg);
        cudaMemsetAsync(xout, 0, (size_t)NN*FF*sizeof(float));
        edge_kernel<<<EE/EPB, ETHREADS, EDGE_SMEM>>>(
            Apre, Bpre, xin, srcp, dstp,
            W1 + (size_t)l*126*128 + 125*128,
            wimg, b2 + (size_t)l*128,
            b3 + (size_t)l*64, xout);
    }
    pool_head_kernel<<<GG, 64>>>(x2, batch, u, LW1, Lb1, LW2, Lb2, LW3, Lb3, out);
}